// round 5
// baseline (speedup 1.0000x reference)
#include <cuda_runtime.h>
#include <cstdint>

// ---------------- problem constants ----------------
#define B_SZ   4096
#define T_SZ   4
#define C_SZ   1024
#define H_SZ   8
#define DH_SZ  128
#define N_QKV  3072
#define SCALE_F 0.08838834764831845f   // 128^-0.5
#define LN_EPS 1e-5f

// ---------------- device scratch (no runtime alloc allowed) ----------------
__device__ float g_Wqkv_t [(size_t)T_SZ * N_QKV * C_SZ];   // [t][n][k]
__device__ float g_Wproj_t[(size_t)T_SZ * C_SZ  * C_SZ];   // [t][n][k]
__device__ float g_qkv    [(size_t)B_SZ * T_SZ * N_QKV];   // [b][t][3C]
__device__ float g_ctx    [(size_t)B_SZ * T_SZ * C_SZ];    // [b][t][C]

// ---------------- helpers ----------------
__device__ __forceinline__ uint32_t smem_u32(const void* p) {
    uint32_t a;
    asm("{ .reg .u64 t; cvta.to.shared.u64 t, %1; cvt.u32.u64 %0, t; }" : "=r"(a) : "l"(p));
    return a;
}
__device__ __forceinline__ uint32_t f2tf(float x) {
    uint32_t r; asm("cvt.rna.tf32.f32 %0, %1;" : "=r"(r) : "f"(x)); return r;
}
__device__ __forceinline__ void mma8(float* c, const uint32_t* a, uint32_t b0, uint32_t b1) {
    asm volatile(
        "mma.sync.aligned.m16n8k8.row.col.f32.tf32.tf32.f32 "
        "{%0,%1,%2,%3}, {%4,%5,%6,%7}, {%8,%9}, {%0,%1,%2,%3};"
        : "+f"(c[0]), "+f"(c[1]), "+f"(c[2]), "+f"(c[3])
        : "r"(a[0]), "r"(a[1]), "r"(a[2]), "r"(a[3]), "r"(b0), "r"(b1));
}
#define CP_ASYNC16(dst, src)  asm volatile("cp.async.cg.shared.global [%0], [%1], 16;" :: "r"(dst), "l"(src))
#define CP_COMMIT()           asm volatile("cp.async.commit_group;" ::: "memory")
#define CP_WAIT1()            asm volatile("cp.async.wait_group 1;" ::: "memory")

// ---------------- GEMM: D[m,n] = sum_k A[m,k] * Wt[t][n][k] (+bias, +resid) ----------------
// A row m lives at A[(m*T + t)*C + k]  (the [B,T,C] layout for fixed t).
static constexpr int MT = 128;
static constexpr int NT = 256;
static constexpr int KT = 32;                       // K per stage
static constexpr int NSTG = 3;
static constexpr int LDP = 36;                      // padded fp32 row stride
static constexpr int A_WORDS = MT * LDP;            // 4608
static constexpr int STG_WORDS = (MT + NT) * LDP;   // 13824
static constexpr int GEMM_SMEM = NSTG * STG_WORDS * 4;   // 165888 B

template <int NTOT, bool RESID>
__global__ __launch_bounds__(256, 1)
void gemm_kernel(const float* __restrict__ A,
                 const float* __restrict__ Wt,
                 const float* __restrict__ bias,
                 const float* __restrict__ resid,
                 float* __restrict__ out) {
    extern __shared__ float sm[];
    const int tid = threadIdx.x;
    const int wid = tid >> 5, lane = tid & 31;
    const int warp_m = wid >> 2;        // 0..1  (64 rows each)
    const int warp_n = wid & 3;         // 0..3  (64 cols each)
    const int g = lane >> 2, q = lane & 3;
    const int n0 = blockIdx.x * NT;
    const int m0 = blockIdx.y * MT;
    const int t  = blockIdx.z;

    auto load_stage = [&](int ck, int slot) {
        const int k0 = ck * KT;
        float* As = sm + slot * STG_WORDS;
        float* Bs = As + A_WORDS;
        #pragma unroll
        for (int p = 0; p < 4; p++) {              // A: 128 rows x 8 float4
            int idx = tid + p * 256;
            int r = idx >> 3, j = idx & 7;
            const float* src = A + ((size_t)(m0 + r) * T_SZ + t) * C_SZ + k0 + j * 4;
            CP_ASYNC16(smem_u32(As + r * LDP + j * 4), src);
        }
        #pragma unroll
        for (int p = 0; p < 8; p++) {              // B: 256 rows x 8 float4
            int idx = tid + p * 256;
            int r = idx >> 3, j = idx & 7;
            const float* src = Wt + ((size_t)t * NTOT + n0 + r) * C_SZ + k0 + j * 4;
            CP_ASYNC16(smem_u32(Bs + r * LDP + j * 4), src);
        }
    };

    float acc[4][8][4];
    #pragma unroll
    for (int mi = 0; mi < 4; mi++)
        #pragma unroll
        for (int ni = 0; ni < 8; ni++)
            #pragma unroll
            for (int c = 0; c < 4; c++) acc[mi][ni][c] = 0.f;

    load_stage(0, 0); CP_COMMIT();
    load_stage(1, 1); CP_COMMIT();

    const int NKC = C_SZ / KT;          // 32
    for (int i = 0; i < NKC; i++) {
        CP_WAIT1();
        __syncthreads();
        const float* As = sm + (i % NSTG) * STG_WORDS;
        const float* Bs = As + A_WORDS;
        #pragma unroll
        for (int ks = 0; ks < 4; ks++) {
            const int k0 = ks * 8;
            uint32_t a[4][4];
            #pragma unroll
            for (int mi = 0; mi < 4; mi++) {
                const float* ap = As + (warp_m * 64 + mi * 16) * LDP + k0;
                a[mi][0] = f2tf(ap[g * LDP + q]);
                a[mi][1] = f2tf(ap[(g + 8) * LDP + q]);
                a[mi][2] = f2tf(ap[g * LDP + q + 4]);
                a[mi][3] = f2tf(ap[(g + 8) * LDP + q + 4]);
            }
            #pragma unroll
            for (int ni = 0; ni < 8; ni++) {
                const float* bp = Bs + (warp_n * 64 + ni * 8 + g) * LDP + k0;
                const uint32_t b0 = f2tf(bp[q]);
                const uint32_t b1 = f2tf(bp[q + 4]);
                #pragma unroll
                for (int mi = 0; mi < 4; mi++) mma8(acc[mi][ni], a[mi], b0, b1);
            }
        }
        if (i + 2 < NKC) load_stage(i + 2, (i + 2) % NSTG);
        CP_COMMIT();
    }

    // epilogue: direct register -> gmem (32B sector-aligned float2 stores)
    #pragma unroll
    for (int mi = 0; mi < 4; mi++) {
        #pragma unroll
        for (int ni = 0; ni < 8; ni++) {
            const int row = m0 + warp_m * 64 + mi * 16 + g;
            const int col = n0 + warp_n * 64 + ni * 8 + q * 2;
            const float2 bb = *reinterpret_cast<const float2*>(bias + (size_t)t * NTOT + col);
            float2 v0 = make_float2(acc[mi][ni][0] + bb.x, acc[mi][ni][1] + bb.y);
            float2 v1 = make_float2(acc[mi][ni][2] + bb.x, acc[mi][ni][3] + bb.y);
            if (RESID) {
                const float2 r0 = *reinterpret_cast<const float2*>(
                    resid + ((size_t)row * T_SZ + t) * C_SZ + col);
                const float2 r1 = *reinterpret_cast<const float2*>(
                    resid + ((size_t)(row + 8) * T_SZ + t) * C_SZ + col);
                v0.x += r0.x; v0.y += r0.y; v1.x += r1.x; v1.y += r1.y;
            }
            *reinterpret_cast<float2*>(out + ((size_t)row * T_SZ + t) * NTOT + col) = v0;
            *reinterpret_cast<float2*>(out + ((size_t)(row + 8) * T_SZ + t) * NTOT + col) = v1;
        }
    }
}

// ---------------- weight transpose: W[t][k][n] -> Wt[t][n][k] ----------------
__global__ __launch_bounds__(256) void transpose_kernel(const float* __restrict__ in,
                                                        float* __restrict__ out,
                                                        int R, int Ncols) {
    __shared__ float tile[32][33];
    const int t = blockIdx.z;
    const float* inp = in + (size_t)t * R * Ncols;
    float* outp = out + (size_t)t * R * Ncols;
    const int n0 = blockIdx.x * 32, r0 = blockIdx.y * 32;
    const int tx = threadIdx.x, ty = threadIdx.y;   // 32 x 8
    #pragma unroll
    for (int i = 0; i < 32; i += 8)
        tile[ty + i][tx] = inp[(size_t)(r0 + ty + i) * Ncols + n0 + tx];
    __syncthreads();
    #pragma unroll
    for (int i = 0; i < 32; i += 8)
        outp[(size_t)(n0 + ty + i) * R + r0 + tx] = tile[tx][ty + i];
}

// ---------------- cross-task attention (T=4; one block per b, warp = head) ----------------
__global__ __launch_bounds__(256) void attn_kernel(const float* __restrict__ qkv,
                                                   float* __restrict__ ctx) {
    const int b = blockIdx.x;
    const int h = threadIdx.x >> 5;     // 8 warps = 8 heads
    const int l = threadIdx.x & 31;
    const size_t base = (size_t)b * T_SZ * N_QKV + h * DH_SZ + l * 4;

    float4 q[4], k[4], v[4];
    #pragma unroll
    for (int tt = 0; tt < 4; tt++) {
        q[tt] = *reinterpret_cast<const float4*>(qkv + base + (size_t)tt * N_QKV);
        k[tt] = *reinterpret_cast<const float4*>(qkv + base + (size_t)tt * N_QKV + C_SZ);
        v[tt] = *reinterpret_cast<const float4*>(qkv + base + (size_t)tt * N_QKV + 2 * C_SZ);
    }
    float s[16];
    #pragma unroll
    for (int qt = 0; qt < 4; qt++)
        #pragma unroll
        for (int kt = 0; kt < 4; kt++)
            s[qt * 4 + kt] = q[qt].x * k[kt].x + q[qt].y * k[kt].y +
                             q[qt].z * k[kt].z + q[qt].w * k[kt].w;
    #pragma unroll
    for (int off = 16; off; off >>= 1)
        #pragma unroll
        for (int i = 0; i < 16; i++)
            s[i] += __shfl_xor_sync(0xffffffffu, s[i], off);

    #pragma unroll
    for (int qt = 0; qt < 4; qt++) {
        float sc[4];
        #pragma unroll
        for (int kt = 0; kt < 4; kt++) sc[kt] = s[qt * 4 + kt] * SCALE_F;
        float mx = fmaxf(fmaxf(sc[0], sc[1]), fmaxf(sc[2], sc[3]));
        float e[4], sum = 0.f;
        #pragma unroll
        for (int kt = 0; kt < 4; kt++) { e[kt] = __expf(sc[kt] - mx); sum += e[kt]; }
        const float inv = 1.f / sum;
        float4 acc = make_float4(0.f, 0.f, 0.f, 0.f);
        #pragma unroll
        for (int kt = 0; kt < 4; kt++) {
            const float a = e[kt] * inv;
            acc.x += a * v[kt].x; acc.y += a * v[kt].y;
            acc.z += a * v[kt].z; acc.w += a * v[kt].w;
        }
        *reinterpret_cast<float4*>(ctx + ((size_t)b * T_SZ + qt) * C_SZ + h * DH_SZ + l * 4) = acc;
    }
}

// ---------------- in-place LayerNorm over C=1024 per (b,t) row ----------------
__global__ __launch_bounds__(256) void ln_kernel(float* __restrict__ x,
                                                 const float* __restrict__ gamma,
                                                 const float* __restrict__ beta) {
    __shared__ float rs[8], rq[8];
    const size_t row = blockIdx.x;
    float4* xr = reinterpret_cast<float4*>(x + row * C_SZ);
    const int tid = threadIdx.x;
    float4 v = xr[tid];
    float s = v.x + v.y + v.z + v.w;
    float qq = v.x * v.x + v.y * v.y + v.z * v.z + v.w * v.w;
    #pragma unroll
    for (int o = 16; o; o >>= 1) {
        s  += __shfl_xor_sync(0xffffffffu, s,  o);
        qq += __shfl_xor_sync(0xffffffffu, qq, o);
    }
    if ((tid & 31) == 0) { rs[tid >> 5] = s; rq[tid >> 5] = qq; }
    __syncthreads();
    float S = 0.f, Q = 0.f;
    #pragma unroll
    for (int i = 0; i < 8; i++) { S += rs[i]; Q += rq[i]; }
    const float mu  = S * (1.f / C_SZ);
    const float var = Q * (1.f / C_SZ) - mu * mu;
    const float inv = rsqrtf(var + LN_EPS);
    const float4 g = reinterpret_cast<const float4*>(gamma)[tid];
    const float4 b = reinterpret_cast<const float4*>(beta)[tid];
    float4 o;
    o.x = (v.x - mu) * inv * g.x + b.x;
    o.y = (v.y - mu) * inv * g.y + b.y;
    o.z = (v.z - mu) * inv * g.z + b.z;
    o.w = (v.w - mu) * inv * g.w + b.w;
    xr[tid] = o;
}

// ---------------- launcher ----------------
extern "C" void kernel_launch(void* const* d_in, const int* in_sizes, int n_in,
                              void* d_out, int out_size) {
    (void)in_sizes; (void)n_in; (void)out_size;
    const float* feats = (const float*)d_in[0];
    const float* Wqkv  = (const float*)d_in[1];
    const float* bqkv  = (const float*)d_in[2];
    const float* Wproj = (const float*)d_in[3];
    const float* bproj = (const float*)d_in[4];
    const float* gamma = (const float*)d_in[5];
    const float* beta  = (const float*)d_in[6];
    float* out = (float*)d_out;

    float *wqkv_t, *wproj_t, *qkv, *ctx;
    cudaGetSymbolAddress((void**)&wqkv_t, g_Wqkv_t);
    cudaGetSymbolAddress((void**)&wproj_t, g_Wproj_t);
    cudaGetSymbolAddress((void**)&qkv, g_qkv);
    cudaGetSymbolAddress((void**)&ctx, g_ctx);

    cudaFuncSetAttribute(gemm_kernel<N_QKV, false>,
                         cudaFuncAttributeMaxDynamicSharedMemorySize, GEMM_SMEM);
    cudaFuncSetAttribute(gemm_kernel<C_SZ, true>,
                         cudaFuncAttributeMaxDynamicSharedMemorySize, GEMM_SMEM);

    // 1. transpose weights into K-major scratch
    transpose_kernel<<<dim3(N_QKV / 32, C_SZ / 32, T_SZ), dim3(32, 8)>>>(Wqkv, wqkv_t, C_SZ, N_QKV);
    transpose_kernel<<<dim3(C_SZ / 32, C_SZ / 32, T_SZ), dim3(32, 8)>>>(Wproj, wproj_t, C_SZ, C_SZ);
    // 2. QKV projection (tf32 mma.sync)
    gemm_kernel<N_QKV, false><<<dim3(N_QKV / NT, B_SZ / MT, T_SZ), 256, GEMM_SMEM>>>(
        feats, wqkv_t, bqkv, nullptr, qkv);
    // 3. cross-task attention
    attn_kernel<<<B_SZ, 256>>>(qkv, ctx);
    // 4. output projection + bias + residual -> d_out
    gemm_kernel<C_SZ, true><<<dim3(C_SZ / NT, B_SZ / MT, T_SZ), 256, GEMM_SMEM>>>(
        ctx, wproj_t, bproj, feats, out);
    // 5. in-place LayerNorm
    ln_kernel<<<B_SZ * T_SZ, 256>>>(out, gamma, beta);
}